// round 4
// baseline (speedup 1.0000x reference)
#include <cuda_runtime.h>
#include <cstdint>

// Shapes: B=16, T=128, N=64, Cin=128, Cout=256, K=3, kt=3, groups=8
// m = b*T + t in [0, 2048); x[b,t,n,c] flat = (m*64 + n)*128 + c
// Scratch S[b][n][t][512]: o<256 -> h2 (pre-conv), o>=256 -> residual
// Wcat[n][c][512]:          o<256 -> Weff[n][o][c], o>=256 -> W_res[o-256][c]

#define EPSF 1e-5f

__device__ float g_Wcat[64UL * 128 * 512];        // 16.8 MB
__device__ float g_S[16UL * 64 * 128 * 512];      // 268 MB scratch

// ---------- f32x2 packed-FMA helpers (Blackwell) ----------
__device__ __forceinline__ unsigned long long ffma2(unsigned long long a,
                                                    unsigned long long b,
                                                    unsigned long long c) {
    unsigned long long d;
    asm("fma.rn.f32x2 %0, %1, %2, %3;" : "=l"(d) : "l"(a), "l"(b), "l"(c));
    return d;
}
__device__ __forceinline__ unsigned long long dupf(float x) {
    unsigned long long d;
    unsigned int bits = __float_as_uint(x);
    asm("mov.b64 %0, {%1, %1};" : "=l"(d) : "r"(bits));
    return d;
}
__device__ __forceinline__ void unpack2(unsigned long long v, float& lo, float& hi) {
    unsigned int a, b;
    asm("mov.b64 {%0, %1}, %2;" : "=r"(a), "=r"(b) : "l"(v));
    lo = __uint_as_float(a);
    hi = __uint_as_float(b);
}

// ---------- K0: build combined weights Wcat[n][c][512] ----------
__global__ void k0_weights(const float* __restrict__ A,
                           const float* __restrict__ dw,
                           const float* __restrict__ Wpw,
                           const float* __restrict__ Wres) {
    int n = blockIdx.x;
    int oslab = blockIdx.y * 64;
    int tid = threadIdx.x;
    __shared__ float rA[3];
    __shared__ float Wt[128 * 65];  // [c][olocal], pad 65 for conflict-free

    if (tid < 3) {
        const float* Ap = A + ((size_t)tid * 64 + n) * 64;
        float s = 0.f;
        #pragma unroll
        for (int m = 0; m < 64; m++) s += Ap[m];
        rA[tid] = s;
    }
    __syncthreads();
    float r0 = rA[0], r1 = rA[1], r2 = rA[2];

    // phase 1: compute (coalesced over c), stage in smem transposed
    for (int it = 0; it < 32; ++it) {
        int idx = tid + it * 256;          // 8192 = 64 o x 128 c
        int c = idx & 127;
        int ol = idx >> 7;                 // 0..63
        int o = oslab + ol;
        float w;
        if (o < 256) {
            w = r0 * dw[c]        * Wpw[(size_t)o * 384 + c]
              + r1 * dw[128 + c]  * Wpw[(size_t)o * 384 + 128 + c]
              + r2 * dw[256 + c]  * Wpw[(size_t)o * 384 + 256 + c];
        } else {
            w = Wres[(size_t)(o - 256) * 128 + c];
        }
        Wt[c * 65 + ol] = w;
    }
    __syncthreads();
    // phase 2: write coalesced over o
    for (int it = 0; it < 32; ++it) {
        int idx = tid + it * 256;
        int o = idx & 63;
        int c = idx >> 6;                  // 0..127
        g_Wcat[((size_t)n * 128 + c) * 512 + oslab + o] = Wt[c * 65 + o];
    }
}

// ---------- K1: GEMM  S[b][n][t][o2] = x[b,:,n,:] @ Wcat[n] ----------
// Grid: (ntile=4, b=16, n=64). Block 256. Tile 128(m) x 128(o), K=128.
// Per-thread 8x8 via f32x2 pairs over o.
__global__ __launch_bounds__(256, 1) void k1_gemm(const float* __restrict__ x) {
    extern __shared__ float sm[];
    float* As = sm;                // [m 128][k 128]
    float* Bs = sm + 128 * 128;    // [k 128][o 128]

    int n   = blockIdx.z;
    int bb  = blockIdx.y;          // m0 = bb*128 -> one full batch index b
    int nt0 = blockIdx.x * 128;
    int tid = threadIdx.x;

    int r  = tid >> 5;
    int c4 = (tid & 31) * 4;

    const float* xb = x + (size_t)bb * 128 * 8192 + (size_t)n * 128;
    #pragma unroll
    for (int i = 0; i < 16; i++) {
        int row = r + i * 8;       // t within tile
        float4 v = *reinterpret_cast<const float4*>(xb + (size_t)row * 8192 + c4);
        *reinterpret_cast<float4*>(&As[row * 128 + c4]) = v;
    }
    const float* wb = g_Wcat + (size_t)n * 128 * 512 + nt0;
    #pragma unroll
    for (int i = 0; i < 16; i++) {
        int row = r + i * 8;       // c (=k) index
        float4 v = *reinterpret_cast<const float4*>(wb + (size_t)row * 512 + c4);
        *reinterpret_cast<float4*>(&Bs[row * 128 + c4]) = v;
    }
    __syncthreads();

    int tx = tid & 15;             // o group: 8 outputs
    int ty = tid >> 4;             // m group: 8 rows

    unsigned long long acc[8][4];
    #pragma unroll
    for (int i = 0; i < 8; i++)
        #pragma unroll
        for (int j = 0; j < 4; j++) acc[i][j] = 0ULL;

    for (int k = 0; k < 128; k += 4) {
        float4 a4[8];
        #pragma unroll
        for (int i = 0; i < 8; i++)
            a4[i] = *reinterpret_cast<const float4*>(&As[(ty * 8 + i) * 128 + k]);
        #pragma unroll
        for (int kk = 0; kk < 4; kk++) {
            ulonglong2 b0 = *reinterpret_cast<const ulonglong2*>(&Bs[(k + kk) * 128 + tx * 8]);
            ulonglong2 b1 = *reinterpret_cast<const ulonglong2*>(&Bs[(k + kk) * 128 + tx * 8 + 4]);
            #pragma unroll
            for (int i = 0; i < 8; i++) {
                float av = (kk == 0) ? a4[i].x : (kk == 1) ? a4[i].y
                          : (kk == 2) ? a4[i].z : a4[i].w;
                unsigned long long ad = dupf(av);
                acc[i][0] = ffma2(ad, b0.x, acc[i][0]);
                acc[i][1] = ffma2(ad, b0.y, acc[i][1]);
                acc[i][2] = ffma2(ad, b1.x, acc[i][2]);
                acc[i][3] = ffma2(ad, b1.y, acc[i][3]);
            }
        }
    }

    float* Sb = g_S + ((size_t)(bb * 64 + n)) * 128 * 512 + nt0 + tx * 8;
    #pragma unroll
    for (int i = 0; i < 8; i++) {
        int t = ty * 8 + i;
        float o8[8];
        #pragma unroll
        for (int j = 0; j < 4; j++) unpack2(acc[i][j], o8[2 * j], o8[2 * j + 1]);
        float4* p = reinterpret_cast<float4*>(Sb + (size_t)t * 512);
        p[0] = make_float4(o8[0], o8[1], o8[2], o8[3]);
        p[1] = make_float4(o8[4], o8[5], o8[6], o8[7]);
    }
}

// ---------- K2: fused conv3(T) + GroupNorm + residual + LayerNorm + GELU ----------
// Grid (n=64, b=16), 512 threads. smem tile hs[128 t][256 o].
__global__ __launch_bounds__(512, 1) void k2_fused(const float* __restrict__ Wconv,
                                                   const float* __restrict__ gnw,
                                                   const float* __restrict__ gnb,
                                                   const float* __restrict__ lnw,
                                                   const float* __restrict__ lnb,
                                                   float* __restrict__ out) {
    extern __shared__ float hs[];  // 128*256 floats = 128 KB
    __shared__ float redS[16], redQ[16], gmean[8], ginv[8];

    int n = blockIdx.x, b = blockIdx.y;
    int tid = threadIdx.x;
    const float* Sbn = g_S + (size_t)(b * 64 + n) * 128 * 512;

    // load h2 half of S (contiguous within each 512-row)
    #pragma unroll
    for (int i = 0; i < 16; i++) {
        int idx = tid + i * 512;       // 8192 float4
        int t = idx >> 6;
        int o4 = (idx & 63) * 4;
        *reinterpret_cast<float4*>(&hs[t * 256 + o4]) =
            *reinterpret_cast<const float4*>(Sbn + (size_t)t * 512 + o4);
    }
    __syncthreads();

    int o = tid & 255, h = tid >> 8;   // thread = (channel o, t-half h)
    float w0 = Wconv[o * 3], w1 = Wconv[o * 3 + 1], w2 = Wconv[o * 3 + 2];
    float v[64];
    float s = 0.f, q = 0.f;
    int t0 = h * 64;
    #pragma unroll
    for (int i = 0; i < 64; i++) {
        int t = t0 + i;
        float mid = hs[t * 256 + o];
        float lf  = (t > 0)   ? hs[(t - 1) * 256 + o] : 0.f;
        float rt  = (t < 127) ? hs[(t + 1) * 256 + o] : 0.f;
        float val = fmaf(w0, lf, fmaf(w1, mid, w2 * rt));
        v[i] = val;
        s += val;
        q = fmaf(val, val, q);
    }
    // group stats: each warp = one channel-group x one t-half
    #pragma unroll
    for (int off = 16; off; off >>= 1) {
        s += __shfl_xor_sync(0xFFFFFFFFu, s, off);
        q += __shfl_xor_sync(0xFFFFFFFFu, q, off);
    }
    int warp = tid >> 5, lane = tid & 31;
    if (lane == 0) { redS[warp] = s; redQ[warp] = q; }
    __syncthreads();
    if (tid < 8) {
        float S2 = redS[tid] + redS[tid + 8];
        float Q2 = redQ[tid] + redQ[tid + 8];
        float mean = S2 * (1.f / 4096.f);
        float var = Q2 * (1.f / 4096.f) - mean * mean;
        gmean[tid] = mean;
        ginv[tid] = rsqrtf(var + EPSF);
    }
    __syncthreads();

    int g = o >> 5;
    float inv = ginv[g], mu = gmean[g];
    float sc = inv * gnw[o];
    float sb = gnb[o] - mu * sc;
    const float* Rbn = Sbn + 256;
    #pragma unroll
    for (int i = 0; i < 64; i++) {
        int t = t0 + i;
        float z = fmaf(v[i], sc, sb) + Rbn[(size_t)t * 512 + o];
        hs[t * 256 + o] = z;
    }
    __syncthreads();

    // LayerNorm over o per (t) row + exact GELU, write final output
    float lw[8], lb[8];
    #pragma unroll
    for (int j = 0; j < 8; j++) { lw[j] = lnw[lane + 32 * j]; lb[j] = lnb[lane + 32 * j]; }
    for (int t = warp; t < 128; t += 16) {
        float z[8];
        float s2 = 0.f, q2 = 0.f;
        #pragma unroll
        for (int j = 0; j < 8; j++) {
            z[j] = hs[t * 256 + lane + 32 * j];
            s2 += z[j];
            q2 = fmaf(z[j], z[j], q2);
        }
        #pragma unroll
        for (int off = 16; off; off >>= 1) {
            s2 += __shfl_xor_sync(0xFFFFFFFFu, s2, off);
            q2 += __shfl_xor_sync(0xFFFFFFFFu, q2, off);
        }
        float mean = s2 * (1.f / 256.f);
        float inv2 = rsqrtf(q2 * (1.f / 256.f) - mean * mean + EPSF);
        float* ob = out + ((size_t)(b * 128 + t) * 64 + n) * 256;
        #pragma unroll
        for (int j = 0; j < 8; j++) {
            float u = fmaf((z[j] - mean) * inv2, lw[j], lb[j]);
            ob[lane + 32 * j] = 0.5f * u * (1.f + erff(u * 0.70710678f));
        }
    }
}

extern "C" void kernel_launch(void* const* d_in, const int* in_sizes, int n_in,
                              void* d_out, int out_size) {
    const float* x     = (const float*)d_in[0];
    const float* A     = (const float*)d_in[1];
    const float* dw    = (const float*)d_in[2];
    const float* Wpw   = (const float*)d_in[3];
    const float* Wconv = (const float*)d_in[4];
    const float* gnw   = (const float*)d_in[5];
    const float* gnb   = (const float*)d_in[6];
    const float* lnw   = (const float*)d_in[7];
    const float* lnb   = (const float*)d_in[8];
    const float* Wres  = (const float*)d_in[9];
    float* out = (float*)d_out;

    cudaFuncSetAttribute(k1_gemm,  cudaFuncAttributeMaxDynamicSharedMemorySize, 131072);
    cudaFuncSetAttribute(k2_fused, cudaFuncAttributeMaxDynamicSharedMemorySize, 131072);

    k0_weights<<<dim3(64, 8), 256>>>(A, dw, Wpw, Wres);
    k1_gemm<<<dim3(4, 16, 64), 256, 131072>>>(x);
    k2_fused<<<dim3(64, 16), 512, 131072>>>(Wconv, gnw, gnb, lnw, lnb, out);
}

// round 9
// speedup vs baseline: 1.5936x; 1.5936x over previous
#include <cuda_runtime.h>
#include <cuda_bf16.h>
#include <cstdint>

// Shapes: B=16, T=128, N=64, Cin=128, Cout=256, K=3, kt=3, groups=8
// Per-CTA (b,n): C[128 t][512 vcol] = X[128x128] @ Wcat[n][vcol][c]^T, split-bf16 (3 K-sections).
//   vcol<256: h2 (pre-conv)   vcol>=256: residual
// g_Bw[n][part(0=hi,1=lo)][vcol 512][k 128] bf16

#define EPSF 1e-5f
// XOR-swizzled smem tile hs[128 t][256 o]: conflict-free column- and row-major access
#define HS(t,o) ((t)*256 + (((o) & ~31) | (((o) ^ (t)) & 31)))

__device__ __nv_bfloat16 g_Bw[64UL * 2 * 512 * 128];   // 16.8 MB

// ---------------- helpers ----------------
__device__ __forceinline__ uint32_t s2u(const void* p) {
    uint32_t a;
    asm("{ .reg .u64 t; cvta.to.shared.u64 t, %1; cvt.u32.u64 %0, t; }" : "=r"(a) : "l"(p));
    return a;
}
__device__ __forceinline__ void ldmA(uint32_t* a, uint32_t addr) {
    asm volatile("ldmatrix.sync.aligned.m8n8.x4.shared.b16 {%0,%1,%2,%3}, [%4];"
                 : "=r"(a[0]), "=r"(a[1]), "=r"(a[2]), "=r"(a[3]) : "r"(addr));
}
__device__ __forceinline__ void ldmB(uint32_t* bq, uint32_t addr) {
    asm volatile("ldmatrix.sync.aligned.m8n8.x2.shared.b16 {%0,%1}, [%2];"
                 : "=r"(bq[0]), "=r"(bq[1]) : "r"(addr));
}
__device__ __forceinline__ void mma16816(float* c, const uint32_t* a, const uint32_t* bq) {
    asm volatile("mma.sync.aligned.m16n8k16.row.col.f32.bf16.bf16.f32 "
                 "{%0,%1,%2,%3}, {%4,%5,%6,%7}, {%8,%9}, {%0,%1,%2,%3};"
                 : "+f"(c[0]), "+f"(c[1]), "+f"(c[2]), "+f"(c[3])
                 : "r"(a[0]), "r"(a[1]), "r"(a[2]), "r"(a[3]), "r"(bq[0]), "r"(bq[1]));
}
__device__ __forceinline__ void cpa16(uint32_t dst, const void* src) {
    asm volatile("cp.async.cg.shared.global [%0], [%1], 16;"
                 :: "r"(dst), "l"((unsigned long long)__cvta_generic_to_global(src)));
}
#define CPA_COMMIT() asm volatile("cp.async.commit_group;" ::: "memory")
#define CPA_WAIT1()  asm volatile("cp.async.wait_group 1;" ::: "memory")
#define CPA_WAIT0()  asm volatile("cp.async.wait_group 0;" ::: "memory")

__device__ __forceinline__ uint32_t packbf(float a, float b) {
    __nv_bfloat162 h = __floats2bfloat162_rn(a, b);   // low half = a
    return *(uint32_t*)&h;
}

// ---------------- K0: build bf16 hi/lo weight image ----------------
// Weff[n][v][c] = sum_k rowA[k,n]*dw[k,c]*Wpw[v, k*128+c]  (v<256);  Wres[v-256][c] (v>=256)
__global__ void k0_weights(const float* __restrict__ A, const float* __restrict__ dw,
                           const float* __restrict__ Wpw, const float* __restrict__ Wres) {
    int n = blockIdx.x;
    int vBase = blockIdx.y * 256;
    int tid = threadIdx.x;
    __shared__ float rA[3];
    if (tid < 3) {
        const float* Ap = A + (size_t)tid * 4096 + n * 64;
        float s = 0.f;
        #pragma unroll
        for (int m = 0; m < 64; m++) s += Ap[m];
        rA[tid] = s;
    }
    __syncthreads();
    float r0 = rA[0], r1 = rA[1], r2 = rA[2];
    uint32_t* dhi = (uint32_t*)g_Bw + (size_t)n * 65536;   // 2*512*128 bf16 = 65536 u32 per n
    uint32_t* dlo = dhi + 32768;

    for (int it = 0; it < 64; it++) {
        int idx = tid + it * 256;
        int c2 = idx & 63;
        int v = vBase + (idx >> 6);
        int c = c2 * 2;
        float wa, wb;
        if (v < 256) {
            wa = r0 * dw[c]       * Wpw[(size_t)v * 384 + c]
               + r1 * dw[128 + c] * Wpw[(size_t)v * 384 + 128 + c]
               + r2 * dw[256 + c] * Wpw[(size_t)v * 384 + 256 + c];
            wb = r0 * dw[c + 1]   * Wpw[(size_t)v * 384 + c + 1]
               + r1 * dw[129 + c] * Wpw[(size_t)v * 384 + 129 + c]
               + r2 * dw[257 + c] * Wpw[(size_t)v * 384 + 257 + c];
        } else {
            wa = Wres[(size_t)(v - 256) * 128 + c];
            wb = Wres[(size_t)(v - 256) * 128 + c + 1];
        }
        float ha = __bfloat162float(__float2bfloat16(wa));
        float hb = __bfloat162float(__float2bfloat16(wb));
        dhi[v * 64 + c2] = packbf(wa, wb);
        dlo[v * 64 + c2] = packbf(wa - ha, wb - hb);
    }
}

// ---------------- K_MAIN ----------------
// 256 threads, 8 warps: warp grid 4(M) x 2(N); warp tile 32x64; slice tile 128x128.
// Dyn smem (1024-aligned): xhi[32K] | xlo[32K] | Bbuf0[16K] | Bbuf1[16K] | hs[128K] = 224KB
__global__ __launch_bounds__(256, 1) void k_main(
    const float* __restrict__ x, const float* __restrict__ Wconv,
    const float* __restrict__ gnw, const float* __restrict__ gnb,
    const float* __restrict__ lnw, const float* __restrict__ lnb,
    float* __restrict__ out)
{
    extern __shared__ char dyn[];
    uint32_t dynBase = s2u(dyn);
    uint32_t base = (dynBase + 1023u) & ~1023u;
    char* smemc = dyn + (base - dynBase);
    float* hs = (float*)(smemc + 98304);

    int n = blockIdx.x, b = blockIdx.y;
    int tid = threadIdx.x;
    int w = tid >> 5, l = tid & 31;
    int m0 = (w >> 1) * 32;          // warp M origin
    int n0 = (w & 1) * 64;           // warp N origin within slice

    // ---- load x tile [128 t][128 c], split hi/lo bf16, XOR-swizzled rows (256B, 16B chunks) ----
    {
        int cq = tid & 31, tr = tid >> 5;
        const float* xb = x + (size_t)b * 1048576 + (size_t)n * 128;
        #pragma unroll
        for (int i = 0; i < 16; i++) {
            int t = tr + i * 8;
            float4 v = *(const float4*)(xb + (size_t)t * 8192 + cq * 4);
            float hx = __bfloat162float(__float2bfloat16(v.x));
            float hy = __bfloat162float(__float2bfloat16(v.y));
            float hz = __bfloat162float(__float2bfloat16(v.z));
            float hw = __bfloat162float(__float2bfloat16(v.w));
            uint32_t h0 = packbf(v.x, v.y), h1 = packbf(v.z, v.w);
            uint32_t l0 = packbf(v.x - hx, v.y - hy), l1 = packbf(v.z - hz, v.w - hw);
            int ch = cq >> 1;
            uint32_t off = (uint32_t)t * 256u + (uint32_t)((ch ^ (t & 7)) << 4) + (uint32_t)((cq & 1) * 8);
            *(uint64_t*)(smemc + off)         = (uint64_t)h0 | ((uint64_t)h1 << 32);
            *(uint64_t*)(smemc + 32768 + off) = (uint64_t)l0 | ((uint64_t)l1 << 32);
        }
    }

    const __nv_bfloat16* Bn = g_Bw + (size_t)n * 131072;   // [part][512][128]

    // chunk j (0..5): sec=j>>1, kc=j&1;  B part = (sec==2);  A section = xlo iff sec==1
#define ISSUE_CHUNK(s, j) do {                                                         \
    int part_ = (((j) >> 1) == 2) ? 1 : 0;                                             \
    int kc_ = (j) & 1;                                                                 \
    const char* bsrc_ = (const char*)(Bn + (size_t)part_ * 65536) + (size_t)(s) * 32768 + kc_ * 128; \
    uint32_t dstb_ = base + 65536u + (uint32_t)((j) & 1) * 16384u;                     \
    _Pragma("unroll")                                                                  \
    for (int it_ = 0; it_ < 4; it_++) {                                                \
        int flat_ = tid + it_ * 256;                                                   \
        int ch_ = flat_ & 7, orow_ = flat_ >> 3;                                       \
        cpa16(dstb_ + (uint32_t)orow_ * 128u + (uint32_t)((ch_ ^ (orow_ & 7)) << 4),   \
              bsrc_ + (size_t)orow_ * 256 + ch_ * 16);                                 \
    }                                                                                  \
} while (0)

#define COMPUTE_CHUNK(j, acc) do {                                                     \
    int kc_ = (j) & 1;                                                                 \
    uint32_t asec_ = (((j) >> 1) == 1) ? 32768u : 0u;                                  \
    uint32_t bbase_ = base + 65536u + (uint32_t)((j) & 1) * 16384u;                    \
    _Pragma("unroll")                                                                  \
    for (int kk_ = 0; kk_ < 4; kk_++) {                                                \
        uint32_t af_[2][4];                                                            \
        _Pragma("unroll")                                                              \
        for (int mt_ = 0; mt_ < 2; mt_++) {                                            \
            int m_ = m0 + mt_ * 16 + (l & 15);                                         \
            int ch_ = kc_ * 8 + kk_ * 2 + (l >> 4);                                    \
            ldmA(af_[mt_], base + asec_ + (uint32_t)m_ * 256u + (uint32_t)((ch_ ^ (m_ & 7)) << 4)); \
        }                                                                              \
        uint32_t bg_[8][2];                                                            \
        _Pragma("unroll")                                                              \
        for (int nt_ = 0; nt_ < 8; nt_++) {                                            \
            int orow_ = n0 + nt_ * 8 + (l & 7);                                        \
            int ch_ = kk_ * 2 + ((l >> 3) & 1);                                        \
            ldmB(bg_[nt_], bbase_ + (uint32_t)orow_ * 128u + (uint32_t)((ch_ ^ (orow_ & 7)) << 4)); \
        }                                                                              \
        _Pragma("unroll")                                                              \
        for (int mt_ = 0; mt_ < 2; mt_++)                                              \
            _Pragma("unroll")                                                          \
            for (int nt_ = 0; nt_ < 8; nt_++)                                          \
                mma16816(&(acc)[(mt_ * 8 + nt_) * 4], af_[mt_], bg_[nt_]);             \
    }                                                                                  \
} while (0)

#define RUN_SLICE(s, acc) do {                                                         \
    ISSUE_CHUNK(s, 0); CPA_COMMIT();                                                   \
    _Pragma("unroll")                                                                  \
    for (int j_ = 0; j_ < 6; j_++) {                                                   \
        if (j_ < 5) { ISSUE_CHUNK(s, j_ + 1); CPA_COMMIT(); CPA_WAIT1(); }             \
        else CPA_WAIT0();                                                              \
        __syncthreads();                                                               \
        COMPUTE_CHUNK(j_, acc);                                                        \
        __syncthreads();                                                               \
    }                                                                                  \
} while (0)

#define ZERO64(a) { _Pragma("unroll") for (int z_ = 0; z_ < 64; z_++) (a)[z_] = 0.f; }

#define FLUSH_HS(acc, sBase) do {                                                      \
    _Pragma("unroll")                                                                  \
    for (int mt_ = 0; mt_ < 2; mt_++)                                                  \
    { _Pragma("unroll")                                                                \
      for (int nt_ = 0; nt_ < 8; nt_++) {                                              \
        int t_ = m0 + mt_ * 16 + (l >> 2);                                             \
        int o_ = (sBase) + n0 + nt_ * 8 + (l & 3) * 2;                                 \
        hs[HS(t_, o_)]         = (acc)[(mt_*8+nt_)*4 + 0];                             \
        hs[HS(t_, o_ + 1)]     = (acc)[(mt_*8+nt_)*4 + 1];                             \
        hs[HS(t_ + 8, o_)]     = (acc)[(mt_*8+nt_)*4 + 2];                             \
        hs[HS(t_ + 8, o_ + 1)] = (acc)[(mt_*8+nt_)*4 + 3];                             \
    } }                                                                                \
} while (0)

    // ---- 4 N-slices: 0,1 = h2 -> smem; 2,3 = residual -> registers ----
    float res0[64], res1[64];
    {
        float acc[64];
        ZERO64(acc); RUN_SLICE(0, acc); FLUSH_HS(acc, 0);
        ZERO64(acc); RUN_SLICE(1, acc); FLUSH_HS(acc, 128);
    }
    ZERO64(res0); RUN_SLICE(2, res0);
    ZERO64(res1); RUN_SLICE(3, res1);
    __syncthreads();

    // ---- E1: depthwise conv3 over T (in place, rolling regs) + GroupNorm (warp == group) ----
    {
        int o = tid;                       // 0..255; warp w covers channels of group w
        float cw0 = Wconv[o * 3], cw1 = Wconv[o * 3 + 1], cw2 = Wconv[o * 3 + 2];
        float s = 0.f, q = 0.f;
        float lf = 0.f, cur = hs[HS(0, o)];
        #pragma unroll 4
        for (int t = 0; t < 128; t++) {
            float rt = (t < 127) ? hs[HS(t + 1, o)] : 0.f;
            float val = fmaf(cw0, lf, fmaf(cw1, cur, cw2 * rt));
            hs[HS(t, o)] = val;
            s += val;
            q = fmaf(val, val, q);
            lf = cur; cur = rt;
        }
        #pragma unroll
        for (int off = 16; off; off >>= 1) {
            s += __shfl_xor_sync(0xFFFFFFFFu, s, off);
            q += __shfl_xor_sync(0xFFFFFFFFu, q, off);
        }
        float mean = s * (1.f / 4096.f);
        float inv = rsqrtf(q * (1.f / 4096.f) - mean * mean + EPSF);
        float sc = inv * gnw[o];
        float sb = gnb[o] - mean * sc;
        #pragma unroll 4
        for (int t = 0; t < 128; t++) hs[HS(t, o)] = fmaf(hs[HS(t, o)], sc, sb);
    }
    __syncthreads();

    // ---- E2: add residual from registers ----
    #pragma unroll
    for (int mt = 0; mt < 2; mt++)
    {
        #pragma unroll
        for (int nt = 0; nt < 8; nt++) {
            int t = m0 + mt * 16 + (l >> 2);
            int o0 = n0 + nt * 8 + (l & 3) * 2;
            int i4 = (mt * 8 + nt) * 4;
            hs[HS(t, o0)]           += res0[i4 + 0];
            hs[HS(t, o0 + 1)]       += res0[i4 + 1];
            hs[HS(t + 8, o0)]       += res0[i4 + 2];
            hs[HS(t + 8, o0 + 1)]   += res0[i4 + 3];
            hs[HS(t, 128 + o0)]     += res1[i4 + 0];
            hs[HS(t, 129 + o0)]     += res1[i4 + 1];
            hs[HS(t + 8, 128 + o0)] += res1[i4 + 2];
            hs[HS(t + 8, 129 + o0)] += res1[i4 + 3];
        }
    }
    __syncthreads();

    // ---- E3: LayerNorm over 256 channels per t-row + exact GELU + coalesced store ----
    {
        float lw[8], lb[8];
        #pragma unroll
        for (int j = 0; j < 8; j++) { lw[j] = lnw[l + 32 * j]; lb[j] = lnb[l + 32 * j]; }
        for (int t = w; t < 128; t += 8) {
            float z[8];
            float s = 0.f, q = 0.f;
            #pragma unroll
            for (int j = 0; j < 8; j++) {
                z[j] = hs[HS(t, l + 32 * j)];
                s += z[j];
                q = fmaf(z[j], z[j], q);
            }
            #pragma unroll
            for (int off = 16; off; off >>= 1) {
                s += __shfl_xor_sync(0xFFFFFFFFu, s, off);
                q += __shfl_xor_sync(0xFFFFFFFFu, q, off);
            }
            float mean = s * (1.f / 256.f);
            float inv = rsqrtf(q * (1.f / 256.f) - mean * mean + EPSF);
            float* ob = out + ((size_t)(b * 128 + t) * 64 + n) * 256;
            #pragma unroll
            for (int j = 0; j < 8; j++) {
                float u = fmaf((z[j] - mean) * inv, lw[j], lb[j]);
                ob[l + 32 * j] = 0.5f * u * (1.f + erff(u * 0.70710678f));
            }
        }
    }
}

extern "C" void kernel_launch(void* const* d_in, const int* in_sizes, int n_in,
                              void* d_out, int out_size) {
    const float* x     = (const float*)d_in[0];
    const float* A     = (const float*)d_in[1];
    const float* dw    = (const float*)d_in[2];
    const float* Wpw   = (const float*)d_in[3];
    const float* Wconv = (const float*)d_in[4];
    const float* gnw   = (const float*)d_in[5];
    const float* gnb   = (const float*)d_in[6];
    const float* lnw   = (const float*)d_in[7];
    const float* lnb   = (const float*)d_in[8];
    const float* Wres  = (const float*)d_in[9];
    float* out = (float*)d_out;

    cudaFuncSetAttribute(k_main, cudaFuncAttributeMaxDynamicSharedMemorySize, 229376);

    k0_weights<<<dim3(64, 2), 256>>>(A, dw, Wpw, Wres);
    k_main<<<dim3(64, 16), 256, 229376>>>(x, Wconv, gnw, gnb, lnw, lnb, out);
}